// round 1
// baseline (speedup 1.0000x reference)
#include <cuda_runtime.h>
#include <math.h>

#define Nn 2000
#define Cc 256
#define Hh 8
#define Dd 32
#define LD 2048
#define N3C 768

// ---------------- scratch (static __device__, no allocation) ----------------
__device__ float g_qkv[2][Nn * N3C];      // raw qkv for cls/reg
__device__ float g_q[2][Hh * Nn * Dd];    // normalized q (cls,reg), layout [h][n][d]
__device__ float g_k[2][Hh * Nn * Dd];    // normalized k (cls,reg)
__device__ float g_vn[Hh * Nn * Dd];      // normalized v_cls
__device__ float g_v[Hh * Nn * Dd];       // raw v_cls
__device__ float g_e1[Nn * LD];           // exp(cls logits) current head
__device__ float g_e2[Nn * LD];           // exp(reg logits) current head
__device__ float g_attn[Nn * LD];         // sum over heads of masked attn
__device__ float g_raw[Nn * LD];          // sum over heads of v_norm @ v_norm^T
__device__ float g_S[2][Hh * Nn];         // softmax row sums per head (cls,reg)

// ---------------- zero row sums ----------------
__global__ void k_zeroS() {
    int i = blockIdx.x * 256 + threadIdx.x;
    if (i < Hh * Nn) { g_S[0][i] = 0.f; g_S[1][i] = 0.f; }
}

// ---------------- QKV GEMM: [2000,256] @ [256,768], z=0 cls, z=1 reg --------
__global__ __launch_bounds__(256) void k_gemm(const float* __restrict__ xc,
                                              const float* __restrict__ wc,
                                              const float* __restrict__ xr,
                                              const float* __restrict__ wr) {
    __shared__ float sa[128][33];
    __shared__ float sb[32][129];
    int z = blockIdx.z;
    const float* A = z ? xr : xc;
    const float* B = z ? wr : wc;
    float* Cout = g_qkv[z];
    int t = threadIdx.x, ty = t >> 4, tx = t & 15;
    int r0 = blockIdx.y * 128, c0 = blockIdx.x * 128;
    float acc[8][8];
#pragma unroll
    for (int i = 0; i < 8; i++)
#pragma unroll
        for (int j = 0; j < 8; j++) acc[i][j] = 0.f;

    for (int kk0 = 0; kk0 < Cc; kk0 += 32) {
        __syncthreads();
#pragma unroll
        for (int i = 0; i < 16; i++) {
            int idx = t + i * 256; int ar = idx >> 5, ad = idx & 31;
            int gr = r0 + ar;
            sa[ar][ad] = (gr < Nn) ? A[gr * Cc + kk0 + ad] : 0.f;
        }
#pragma unroll
        for (int i = 0; i < 16; i++) {
            int idx = t + i * 256; int br = idx >> 7, bc = idx & 127;
            sb[br][bc] = B[(kk0 + br) * N3C + c0 + bc];
        }
        __syncthreads();
#pragma unroll
        for (int kk = 0; kk < 32; kk++) {
            float a[8], b[8];
#pragma unroll
            for (int i = 0; i < 8; i++) a[i] = sa[ty + 16 * i][kk];
#pragma unroll
            for (int j = 0; j < 8; j++) b[j] = sb[kk][tx + 16 * j];
#pragma unroll
            for (int i = 0; i < 8; i++)
#pragma unroll
                for (int j = 0; j < 8; j++) acc[i][j] = fmaf(a[i], b[j], acc[i][j]);
        }
    }
#pragma unroll
    for (int i = 0; i < 8; i++) {
        int gr = r0 + ty + 16 * i;
        if (gr < Nn)
#pragma unroll
            for (int j = 0; j < 8; j++)
                Cout[gr * N3C + c0 + tx + 16 * j] = acc[i][j];
    }
}

// ---------------- normalize + split heads, emit x_ori + zero x region ------
__device__ __forceinline__ float rnorm_of(float x) {
    float s = x * x;
#pragma unroll
    for (int off = 16; off; off >>= 1) s += __shfl_xor_sync(0xffffffffu, s, off);
    return 1.f / (sqrtf(s) + 1e-8f);
}

__global__ __launch_bounds__(256) void k_norm(float* __restrict__ out) {
    int n = blockIdx.x;
    int h = threadIdx.x >> 5;
    int d = threadIdx.x & 31;
    const float* qc_row = g_qkv[0] + n * N3C;
    const float* qr_row = g_qkv[1] + n * N3C;
    float qc = qc_row[h * Dd + d];
    float kc = qc_row[Cc + h * Dd + d];
    float vc = qc_row[2 * Cc + h * Dd + d];
    float qr = qr_row[h * Dd + d];
    float kr = qr_row[Cc + h * Dd + d];

    int idx = (h * Nn + n) * Dd + d;
    g_q[0][idx] = qc * rnorm_of(qc);
    g_k[0][idx] = kc * rnorm_of(kc);
    g_q[1][idx] = qr * rnorm_of(qr);
    g_k[1][idx] = kr * rnorm_of(kr);
    g_vn[idx]   = vc * rnorm_of(vc);
    g_v[idx]    = vc;

    out[n * 2 * Cc + h * Dd + d] = 0.f;         // x region zeroed (atomics target)
    out[n * 2 * Cc + Cc + h * Dd + d] = vc;     // x_ori
}

// ---------------- per-head: 3 GEMMs (cls, reg, raw) + exp + row sums -------
__global__ __launch_bounds__(256) void k_logits(int h) {
    __shared__ float sa[128][33];
    __shared__ float sb[128][33];
    int t = threadIdx.x, ty = t >> 4, tx = t & 15;
    int r0 = blockIdx.y * 128, c0 = blockIdx.x * 128;

    for (int p = 0; p < 3; p++) {
        const float* A = (p == 0) ? g_q[0] : (p == 1) ? g_q[1] : g_vn;
        const float* B = (p == 0) ? g_k[0] : (p == 1) ? g_k[1] : g_vn;
        A += h * Nn * Dd;
        B += h * Nn * Dd;
        __syncthreads();
#pragma unroll
        for (int i = 0; i < 16; i++) {
            int idx = t + i * 256; int rr = idx >> 5, dd = idx & 31;
            sa[rr][dd] = (r0 + rr < Nn) ? A[(r0 + rr) * Dd + dd] : 0.f;
            sb[rr][dd] = (c0 + rr < Nn) ? B[(c0 + rr) * Dd + dd] : 0.f;
        }
        __syncthreads();
        float acc[8][8];
#pragma unroll
        for (int i = 0; i < 8; i++)
#pragma unroll
            for (int j = 0; j < 8; j++) acc[i][j] = 0.f;
#pragma unroll
        for (int kk = 0; kk < 32; kk++) {
            float a[8], b[8];
#pragma unroll
            for (int i = 0; i < 8; i++) a[i] = sa[ty + 16 * i][kk];
#pragma unroll
            for (int j = 0; j < 8; j++) b[j] = sb[tx + 16 * j][kk];
#pragma unroll
            for (int i = 0; i < 8; i++)
#pragma unroll
                for (int j = 0; j < 8; j++) acc[i][j] = fmaf(a[i], b[j], acc[i][j]);
        }

        if (p < 2) {
            float* E = p ? g_e2 : g_e1;
            float* S = g_S[p] + h * Nn;
#pragma unroll
            for (int i = 0; i < 8; i++) {
                int r = r0 + ty + 16 * i;
                float rs = 0.f;
#pragma unroll
                for (int j = 0; j < 8; j++) {
                    int c = c0 + tx + 16 * j;
                    float e = __expf(25.f * acc[i][j] - 25.f);
                    if (c >= Nn) e = 0.f;
                    rs += e;
                    if (r < Nn && c < Nn) E[r * LD + c] = e;
                }
                rs += __shfl_down_sync(0xffffffffu, rs, 8, 16);
                rs += __shfl_down_sync(0xffffffffu, rs, 4, 16);
                rs += __shfl_down_sync(0xffffffffu, rs, 2, 16);
                rs += __shfl_down_sync(0xffffffffu, rs, 1, 16);
                if (tx == 0 && r < Nn) atomicAdd(&S[r], rs);
            }
        } else {
#pragma unroll
            for (int i = 0; i < 8; i++) {
                int r = r0 + ty + 16 * i;
                if (r >= Nn) continue;
#pragma unroll
                for (int j = 0; j < 8; j++) {
                    int c = c0 + tx + 16 * j;
                    if (c < Nn) {
                        int g = r * LD + c;
                        g_raw[g] = h ? (g_raw[g] + acc[i][j]) : acc[i][j];
                    }
                }
            }
        }
    }
}

// ---------------- per-head: weights + mask + attn_sum + x = w @ v ----------
__global__ __launch_bounds__(256) void k_wx(int h, float* __restrict__ out) {
    __shared__ float invS1[64], invS2[64];
    __shared__ float w_sm[64][64];
    __shared__ float v_sm[64][32];
    int t = threadIdx.x;
    int r0 = blockIdx.y * 64;
    int mc = blockIdx.x * 256;

    if (t < 64) {
        int r = r0 + t;
        invS1[t] = (r < Nn) ? 1.f / g_S[0][h * Nn + r] : 0.f;
    } else if (t < 128) {
        int r = r0 + t - 64;
        invS2[t - 64] = (r < Nn) ? 1.f / g_S[1][h * Nn + r] : 0.f;
    }
    int d = t & 31, rg = t >> 5;
    float acc[8];
#pragma unroll
    for (int i = 0; i < 8; i++) acc[i] = 0.f;

    for (int mt = 0; mt < 4; mt++) {
        int m0 = mc + mt * 64;
        __syncthreads();
        // phase A: compute weights tile + accumulate attn_sum
#pragma unroll
        for (int i = 0; i < 16; i++) {
            int idx = t + i * 256; int rr = idx >> 6, mm = idx & 63;
            int r = r0 + rr, m = m0 + mm;
            float w = 0.f;
            if (r < Nn && m < Nn) {
                int g = r * LD + m;
                float e1 = g_e1[g], e2 = g_e2[g];
                w = 0.5f * (e1 * invS1[rr] + e2 * invS2[rr]);
                int bs = (r / 10) * 10;
                if (m >= bs && m < bs + 9 && m != r) w = 0.f;
                g_attn[g] = h ? (g_attn[g] + w) : w;
            }
            w_sm[rr][mm] = w;
        }
#pragma unroll
        for (int i = 0; i < 8; i++) {
            int idx = t + i * 256; int mm = idx >> 5, dd = idx & 31;
            v_sm[mm][dd] = (m0 + mm < Nn) ? g_v[(h * Nn + m0 + mm) * Dd + dd] : 0.f;
        }
        __syncthreads();
        // phase B: x += w @ v  (thread: 8 rows x 1 d)
#pragma unroll
        for (int m4 = 0; m4 < 16; m4++) {
            float v0 = v_sm[m4 * 4 + 0][d];
            float v1 = v_sm[m4 * 4 + 1][d];
            float v2 = v_sm[m4 * 4 + 2][d];
            float v3 = v_sm[m4 * 4 + 3][d];
#pragma unroll
            for (int i = 0; i < 8; i++) {
                float4 w4 = *reinterpret_cast<const float4*>(&w_sm[rg * 8 + i][m4 * 4]);
                acc[i] = fmaf(w4.x, v0, acc[i]);
                acc[i] = fmaf(w4.y, v1, acc[i]);
                acc[i] = fmaf(w4.z, v2, acc[i]);
                acc[i] = fmaf(w4.w, v3, acc[i]);
            }
        }
    }
#pragma unroll
    for (int i = 0; i < 8; i++) {
        int r = r0 + rg * 8 + i;
        if (r < Nn) atomicAdd(&out[r * 2 * Cc + h * Dd + d], acc[i]);
    }
}

// ---------------- final similarity softmax + masked renorm -----------------
__global__ __launch_bounds__(256) void k_sim(float* __restrict__ out) {
    __shared__ float e_row[Nn];
    __shared__ float red[2][8];
    int r = blockIdx.x, t = threadIdx.x;
    float se = 0.f, sm = 0.f;
    for (int m = t; m < Nn; m += 256) {
        float e = __expf(g_attn[r * LD + m] * 0.125f);
        e_row[m] = e;
        se += e;
        if (g_raw[r * LD + m] > 6.0f) sm += e;
    }
#pragma unroll
    for (int off = 16; off; off >>= 1) {
        se += __shfl_xor_sync(0xffffffffu, se, off);
        sm += __shfl_xor_sync(0xffffffffu, sm, off);
    }
    int wid = t >> 5, lane = t & 31;
    if (!lane) { red[0][wid] = se; red[1][wid] = sm; }
    __syncthreads();
    if (t == 0) {
        float a = 0.f, b = 0.f;
        for (int i = 0; i < 8; i++) { a += red[0][i]; b += red[1][i]; }
        red[0][0] = a; red[1][0] = b;
    }
    __syncthreads();
    float S = red[0][0], Sm = red[1][0];
    float invS = 1.f / S;
    float invden = 1.f / (Sm * invS + 1e-8f);
    for (int m = t; m < Nn; m += 256) {
        float o = 0.f;
        if (g_raw[r * LD + m] > 6.0f) o = e_row[m] * invS * invden;
        out[Nn * 2 * Cc + r * Nn + m] = o;
    }
}

// ---------------- launch ----------------------------------------------------
extern "C" void kernel_launch(void* const* d_in, const int* in_sizes, int n_in,
                              void* d_out, int out_size) {
    const float* x_cls = (const float*)d_in[0];
    const float* x_reg = (const float*)d_in[1];
    const float* W_cls = (const float*)d_in[2];
    const float* W_reg = (const float*)d_in[3];
    float* out = (float*)d_out;

    k_zeroS<<<(Hh * Nn + 255) / 256, 256>>>();
    k_gemm<<<dim3(6, 16, 2), 256>>>(x_cls, W_cls, x_reg, W_reg);
    k_norm<<<Nn, 256>>>(out);
    for (int h = 0; h < Hh; h++) {
        k_logits<<<dim3(16, 16), 256>>>(h);
        k_wx<<<dim3(8, 32), 256>>>(h, out);
    }
    k_sim<<<Nn, 256>>>(out);
}

// round 2
// speedup vs baseline: 1.2657x; 1.2657x over previous
#include <cuda_runtime.h>
#include <math.h>

#define Nn 2000
#define Cc 256
#define Hh 8
#define Dd 32
#define LD 2048
#define N3C 768

// ---------------- scratch (static __device__, no allocation) ----------------
__device__ float g_qkv[2][Nn * N3C];      // raw qkv for cls/reg
__device__ float g_q[2][Hh * Nn * Dd];    // normalized q (cls,reg), layout [h][n][d]
__device__ float g_k[2][Hh * Nn * Dd];    // normalized k (cls,reg)
__device__ float g_vn[Hh * Nn * Dd];      // normalized v_cls
__device__ float g_v[Hh * Nn * Dd];       // raw v_cls
__device__ float g_e1[Nn * LD];           // exp(cls logits) current head
__device__ float g_e2[Nn * LD];           // exp(reg logits) current head
__device__ float g_attn[Nn * LD];         // sum over heads of masked attn
__device__ float g_raw[Nn * LD];          // sum over heads of v_norm @ v_norm^T
__device__ float g_S[2][Hh * Nn];         // softmax row sums per head (cls,reg)

// ---------------- zero row sums ----------------
__global__ void k_zeroS() {
    int i = blockIdx.x * 256 + threadIdx.x;
    if (i < Hh * Nn) { g_S[0][i] = 0.f; g_S[1][i] = 0.f; }
}

// ---------------- QKV GEMM: [2000,256] @ [256,768], z=0 cls, z=1 reg --------
__global__ __launch_bounds__(256) void k_gemm(const float* __restrict__ xc,
                                              const float* __restrict__ wc,
                                              const float* __restrict__ xr,
                                              const float* __restrict__ wr) {
    __shared__ float sa[32][132];   // k-major A tile (transposed on load)
    __shared__ float sb[32][132];   // k-major B tile (natural layout)
    int z = blockIdx.z;
    const float* A = z ? xr : xc;
    const float* B = z ? wr : wc;
    float* Cout = g_qkv[z];
    int t = threadIdx.x, ty = t >> 4, tx = t & 15;
    int r0 = blockIdx.y * 128, c0 = blockIdx.x * 128;
    float acc[8][8];
#pragma unroll
    for (int i = 0; i < 8; i++)
#pragma unroll
        for (int j = 0; j < 8; j++) acc[i][j] = 0.f;

    for (int kk0 = 0; kk0 < Cc; kk0 += 32) {
        __syncthreads();
        // A: 128 rows x 32 k -> transposed store
#pragma unroll
        for (int i = 0; i < 4; i++) {
            int idx = t + i * 256;              // 0..1023
            int rr = idx >> 3, d4 = (idx & 7) * 4;
            float4 av = make_float4(0.f, 0.f, 0.f, 0.f);
            if (r0 + rr < Nn) av = *reinterpret_cast<const float4*>(&A[(r0 + rr) * Cc + kk0 + d4]);
            sa[d4 + 0][rr] = av.x; sa[d4 + 1][rr] = av.y;
            sa[d4 + 2][rr] = av.z; sa[d4 + 3][rr] = av.w;
        }
        // B: 32 k x 128 cols -> direct vector store
#pragma unroll
        for (int i = 0; i < 4; i++) {
            int idx = t + i * 256;
            int rr = idx >> 5, c4 = (idx & 31) * 4;
            float4 bv = *reinterpret_cast<const float4*>(&B[(kk0 + rr) * N3C + c0 + c4]);
            *reinterpret_cast<float4*>(&sb[rr][c4]) = bv;
        }
        __syncthreads();
#pragma unroll
        for (int kk = 0; kk < 32; kk++) {
            float4 a0 = *reinterpret_cast<const float4*>(&sa[kk][ty * 8]);
            float4 a1 = *reinterpret_cast<const float4*>(&sa[kk][ty * 8 + 4]);
            float4 b0 = *reinterpret_cast<const float4*>(&sb[kk][tx * 8]);
            float4 b1 = *reinterpret_cast<const float4*>(&sb[kk][tx * 8 + 4]);
            float a[8] = {a0.x, a0.y, a0.z, a0.w, a1.x, a1.y, a1.z, a1.w};
            float b[8] = {b0.x, b0.y, b0.z, b0.w, b1.x, b1.y, b1.z, b1.w};
#pragma unroll
            for (int i = 0; i < 8; i++)
#pragma unroll
                for (int j = 0; j < 8; j++) acc[i][j] = fmaf(a[i], b[j], acc[i][j]);
        }
    }
#pragma unroll
    for (int i = 0; i < 8; i++) {
        int gr = r0 + ty * 8 + i;
        if (gr < Nn) {
            float* dst = &Cout[gr * N3C + c0 + tx * 8];
            *reinterpret_cast<float4*>(dst) = make_float4(acc[i][0], acc[i][1], acc[i][2], acc[i][3]);
            *reinterpret_cast<float4*>(dst + 4) = make_float4(acc[i][4], acc[i][5], acc[i][6], acc[i][7]);
        }
    }
}

// ---------------- normalize + split heads, emit x_ori + zero x region ------
__device__ __forceinline__ float rnorm_of(float x) {
    float s = x * x;
#pragma unroll
    for (int off = 16; off; off >>= 1) s += __shfl_xor_sync(0xffffffffu, s, off);
    return 1.f / (sqrtf(s) + 1e-8f);
}

__global__ __launch_bounds__(256) void k_norm(float* __restrict__ out) {
    int n = blockIdx.x;
    int h = threadIdx.x >> 5;
    int d = threadIdx.x & 31;
    const float* qc_row = g_qkv[0] + n * N3C;
    const float* qr_row = g_qkv[1] + n * N3C;
    float qc = qc_row[h * Dd + d];
    float kc = qc_row[Cc + h * Dd + d];
    float vc = qc_row[2 * Cc + h * Dd + d];
    float qr = qr_row[h * Dd + d];
    float kr = qr_row[Cc + h * Dd + d];

    int idx = (h * Nn + n) * Dd + d;
    g_q[0][idx] = qc * rnorm_of(qc);
    g_k[0][idx] = kc * rnorm_of(kc);
    g_q[1][idx] = qr * rnorm_of(qr);
    g_k[1][idx] = kr * rnorm_of(kr);
    g_vn[idx]   = vc * rnorm_of(vc);
    g_v[idx]    = vc;

    out[n * 2 * Cc + h * Dd + d] = 0.f;         // x region zeroed (atomics target)
    out[n * 2 * Cc + Cc + h * Dd + d] = vc;     // x_ori
}

// ---------------- per-head: 3 GEMMs (cls, reg, raw) + exp + row sums -------
__global__ __launch_bounds__(256) void k_logits(int h) {
    __shared__ float sa[32][132];
    __shared__ float sb[32][132];
    int t = threadIdx.x, ty = t >> 4, tx = t & 15;
    int r0 = blockIdx.y * 128, c0 = blockIdx.x * 128;
    bool full_c = (c0 + 128 <= Nn);

    for (int p = 0; p < 3; p++) {
        const float* A = (p == 0) ? g_q[0] : (p == 1) ? g_q[1] : g_vn;
        const float* B = (p == 0) ? g_k[0] : (p == 1) ? g_k[1] : g_vn;
        A += h * Nn * Dd;
        B += h * Nn * Dd;
        __syncthreads();
#pragma unroll
        for (int i = 0; i < 4; i++) {
            int idx = t + i * 256;
            int rr = idx >> 3, d4 = (idx & 7) * 4;
            float4 av = make_float4(0.f, 0.f, 0.f, 0.f);
            float4 bv = make_float4(0.f, 0.f, 0.f, 0.f);
            if (r0 + rr < Nn) av = *reinterpret_cast<const float4*>(&A[(r0 + rr) * Dd + d4]);
            if (c0 + rr < Nn) bv = *reinterpret_cast<const float4*>(&B[(c0 + rr) * Dd + d4]);
            sa[d4 + 0][rr] = av.x; sa[d4 + 1][rr] = av.y;
            sa[d4 + 2][rr] = av.z; sa[d4 + 3][rr] = av.w;
            sb[d4 + 0][rr] = bv.x; sb[d4 + 1][rr] = bv.y;
            sb[d4 + 2][rr] = bv.z; sb[d4 + 3][rr] = bv.w;
        }
        __syncthreads();
        float acc[8][8];
#pragma unroll
        for (int i = 0; i < 8; i++)
#pragma unroll
            for (int j = 0; j < 8; j++) acc[i][j] = 0.f;
#pragma unroll
        for (int kk = 0; kk < 32; kk++) {
            float4 a0 = *reinterpret_cast<const float4*>(&sa[kk][ty * 8]);
            float4 a1 = *reinterpret_cast<const float4*>(&sa[kk][ty * 8 + 4]);
            float4 b0 = *reinterpret_cast<const float4*>(&sb[kk][tx * 8]);
            float4 b1 = *reinterpret_cast<const float4*>(&sb[kk][tx * 8 + 4]);
            float a[8] = {a0.x, a0.y, a0.z, a0.w, a1.x, a1.y, a1.z, a1.w};
            float b[8] = {b0.x, b0.y, b0.z, b0.w, b1.x, b1.y, b1.z, b1.w};
#pragma unroll
            for (int i = 0; i < 8; i++)
#pragma unroll
                for (int j = 0; j < 8; j++) acc[i][j] = fmaf(a[i], b[j], acc[i][j]);
        }

        if (p < 2) {
            float* E = p ? g_e2 : g_e1;
            float* S = g_S[p] + h * Nn;
#pragma unroll
            for (int i = 0; i < 8; i++) {
                int r = r0 + ty * 8 + i;
                float e[8];
                float rs = 0.f;
#pragma unroll
                for (int j = 0; j < 8; j++) {
                    int c = c0 + tx * 8 + j;
                    float ev = __expf(25.f * acc[i][j] - 25.f);
                    if (c >= Nn) ev = 0.f;
                    e[j] = ev;
                    rs += ev;
                }
#pragma unroll
                for (int off = 1; off < 16; off <<= 1)
                    rs += __shfl_xor_sync(0xffffffffu, rs, off);
                if (tx == 0 && r < Nn) atomicAdd(&S[r], rs);
                if (r < Nn) {
                    float* dst = &E[r * LD + c0 + tx * 8];
                    if (full_c) {
                        *reinterpret_cast<float4*>(dst) = make_float4(e[0], e[1], e[2], e[3]);
                        *reinterpret_cast<float4*>(dst + 4) = make_float4(e[4], e[5], e[6], e[7]);
                    } else {
#pragma unroll
                        for (int j = 0; j < 8; j++)
                            if (c0 + tx * 8 + j < Nn) dst[j] = e[j];
                    }
                }
            }
        } else {
#pragma unroll
            for (int i = 0; i < 8; i++) {
                int r = r0 + ty * 8 + i;
                if (r >= Nn) continue;
                float* dst = &g_raw[r * LD + c0 + tx * 8];
                if (full_c) {
                    float4 o0 = make_float4(acc[i][0], acc[i][1], acc[i][2], acc[i][3]);
                    float4 o1 = make_float4(acc[i][4], acc[i][5], acc[i][6], acc[i][7]);
                    if (h) {
                        float4 p0 = *reinterpret_cast<const float4*>(dst);
                        float4 p1 = *reinterpret_cast<const float4*>(dst + 4);
                        o0.x += p0.x; o0.y += p0.y; o0.z += p0.z; o0.w += p0.w;
                        o1.x += p1.x; o1.y += p1.y; o1.z += p1.z; o1.w += p1.w;
                    }
                    *reinterpret_cast<float4*>(dst) = o0;
                    *reinterpret_cast<float4*>(dst + 4) = o1;
                } else {
#pragma unroll
                    for (int j = 0; j < 8; j++) {
                        int c = c0 + tx * 8 + j;
                        if (c < Nn) dst[j] = h ? (dst[j] + acc[i][j]) : acc[i][j];
                    }
                }
            }
        }
    }
}

// ---------------- per-head: weights + mask + attn_sum + x = w @ v ----------
__global__ __launch_bounds__(256) void k_wx(int h, float* __restrict__ out) {
    __shared__ float invS1[64], invS2[64];
    __shared__ float w_sm[64][64];
    __shared__ float v_sm[64][32];
    int t = threadIdx.x;
    int r0 = blockIdx.y * 64;
    int mc = blockIdx.x * 256;

    if (t < 64) {
        int r = r0 + t;
        invS1[t] = (r < Nn) ? 1.f / g_S[0][h * Nn + r] : 0.f;
    } else if (t < 128) {
        int r = r0 + t - 64;
        invS2[t - 64] = (r < Nn) ? 1.f / g_S[1][h * Nn + r] : 0.f;
    }
    int d = t & 31, rg = t >> 5;
    float acc[8];
#pragma unroll
    for (int i = 0; i < 8; i++) acc[i] = 0.f;

    for (int mt = 0; mt < 4; mt++) {
        int m0 = mc + mt * 64;
        __syncthreads();
        // phase A: compute weights tile (float4) + accumulate attn_sum
#pragma unroll
        for (int i = 0; i < 4; i++) {
            int idx = t + i * 256;            // 0..1023
            int rr = idx >> 4, m4 = (idx & 15) * 4;
            int r = r0 + rr, m = m0 + m4;
            float w[4] = {0.f, 0.f, 0.f, 0.f};
            if (r < Nn && m < Nn) {
                int g = r * LD + m;
                float e1v[4], e2v[4];
                bool fullm = (m + 4 <= Nn);
                if (fullm) {
                    float4 a = *reinterpret_cast<const float4*>(&g_e1[g]);
                    float4 b = *reinterpret_cast<const float4*>(&g_e2[g]);
                    e1v[0] = a.x; e1v[1] = a.y; e1v[2] = a.z; e1v[3] = a.w;
                    e2v[0] = b.x; e2v[1] = b.y; e2v[2] = b.z; e2v[3] = b.w;
                } else {
#pragma unroll
                    for (int q = 0; q < 4; q++) {
                        e1v[q] = (m + q < Nn) ? g_e1[g + q] : 0.f;
                        e2v[q] = (m + q < Nn) ? g_e2[g + q] : 0.f;
                    }
                }
                float is1 = invS1[rr], is2 = invS2[rr];
                int bs = (r / 10) * 10;
#pragma unroll
                for (int q = 0; q < 4; q++) {
                    int mm = m + q;
                    if (mm < Nn) {
                        float wv = 0.5f * (e1v[q] * is1 + e2v[q] * is2);
                        if (mm >= bs && mm < bs + 9 && mm != r) wv = 0.f;
                        w[q] = wv;
                    }
                }
                if (fullm) {
                    float4 o = make_float4(w[0], w[1], w[2], w[3]);
                    if (h) {
                        float4 pr = *reinterpret_cast<const float4*>(&g_attn[g]);
                        o.x += pr.x; o.y += pr.y; o.z += pr.z; o.w += pr.w;
                    }
                    *reinterpret_cast<float4*>(&g_attn[g]) = o;
                } else {
#pragma unroll
                    for (int q = 0; q < 4; q++)
                        if (m + q < Nn) g_attn[g + q] = h ? (g_attn[g + q] + w[q]) : w[q];
                }
            }
            *reinterpret_cast<float4*>(&w_sm[rr][m4]) = make_float4(w[0], w[1], w[2], w[3]);
        }
        // v tile: 64 x 32 via float4
#pragma unroll
        for (int i = 0; i < 2; i++) {
            int idx = t + i * 256;            // 0..511
            int mm = idx >> 3, d4 = (idx & 7) * 4;
            float4 vv = make_float4(0.f, 0.f, 0.f, 0.f);
            if (m0 + mm < Nn) vv = *reinterpret_cast<const float4*>(&g_v[(h * Nn + m0 + mm) * Dd + d4]);
            *reinterpret_cast<float4*>(&v_sm[mm][d4]) = vv;
        }
        __syncthreads();
        // phase B: x += w @ v  (thread: 8 rows x 1 d)
#pragma unroll
        for (int m4 = 0; m4 < 16; m4++) {
            float v0 = v_sm[m4 * 4 + 0][d];
            float v1 = v_sm[m4 * 4 + 1][d];
            float v2 = v_sm[m4 * 4 + 2][d];
            float v3 = v_sm[m4 * 4 + 3][d];
#pragma unroll
            for (int i = 0; i < 8; i++) {
                float4 w4 = *reinterpret_cast<const float4*>(&w_sm[rg * 8 + i][m4 * 4]);
                acc[i] = fmaf(w4.x, v0, acc[i]);
                acc[i] = fmaf(w4.y, v1, acc[i]);
                acc[i] = fmaf(w4.z, v2, acc[i]);
                acc[i] = fmaf(w4.w, v3, acc[i]);
            }
        }
    }
#pragma unroll
    for (int i = 0; i < 8; i++) {
        int r = r0 + rg * 8 + i;
        if (r < Nn) atomicAdd(&out[r * 2 * Cc + h * Dd + d], acc[i]);
    }
}

// ---------------- final similarity softmax + masked renorm -----------------
__global__ __launch_bounds__(256) void k_sim(float* __restrict__ out) {
    __shared__ float e_row[Nn];
    __shared__ float red[2][8];
    int r = blockIdx.x, t = threadIdx.x;
    float se = 0.f, sm = 0.f;
    for (int m4 = t * 4; m4 < Nn; m4 += 1024) {
        float4 a = *reinterpret_cast<const float4*>(&g_attn[r * LD + m4]);
        float4 rw = *reinterpret_cast<const float4*>(&g_raw[r * LD + m4]);
        float e0 = __expf(a.x * 0.125f), e1 = __expf(a.y * 0.125f);
        float e2 = __expf(a.z * 0.125f), e3 = __expf(a.w * 0.125f);
        e_row[m4 + 0] = e0; e_row[m4 + 1] = e1;
        e_row[m4 + 2] = e2; e_row[m4 + 3] = e3;
        se += e0 + e1 + e2 + e3;
        if (rw.x > 6.0f) sm += e0;
        if (rw.y > 6.0f) sm += e1;
        if (rw.z > 6.0f) sm += e2;
        if (rw.w > 6.0f) sm += e3;
    }
#pragma unroll
    for (int off = 16; off; off >>= 1) {
        se += __shfl_xor_sync(0xffffffffu, se, off);
        sm += __shfl_xor_sync(0xffffffffu, sm, off);
    }
    int wid = t >> 5, lane = t & 31;
    if (!lane) { red[0][wid] = se; red[1][wid] = sm; }
    __syncthreads();
    if (t == 0) {
        float a = 0.f, b = 0.f;
        for (int i = 0; i < 8; i++) { a += red[0][i]; b += red[1][i]; }
        red[0][0] = a; red[1][0] = b;
    }
    __syncthreads();
    float S = red[0][0], Sm = red[1][0];
    float invS = 1.f / S;
    float invden = 1.f / (Sm * invS + 1e-8f);
    float* orow = &out[Nn * 2 * Cc + r * Nn];
    for (int m4 = t * 4; m4 < Nn; m4 += 1024) {
        float4 rw = *reinterpret_cast<const float4*>(&g_raw[r * LD + m4]);
        float4 o;
        o.x = (rw.x > 6.0f) ? e_row[m4 + 0] * invS * invden : 0.f;
        o.y = (rw.y > 6.0f) ? e_row[m4 + 1] * invS * invden : 0.f;
        o.z = (rw.z > 6.0f) ? e_row[m4 + 2] * invS * invden : 0.f;
        o.w = (rw.w > 6.0f) ? e_row[m4 + 3] * invS * invden : 0.f;
        *reinterpret_cast<float4*>(&orow[m4]) = o;
    }
}

// ---------------- launch ----------------------------------------------------
extern "C" void kernel_launch(void* const* d_in, const int* in_sizes, int n_in,
                              void* d_out, int out_size) {
    const float* x_cls = (const float*)d_in[0];
    const float* x_reg = (const float*)d_in[1];
    const float* W_cls = (const float*)d_in[2];
    const float* W_reg = (const float*)d_in[3];
    float* out = (float*)d_out;

    k_zeroS<<<(Hh * Nn + 255) / 256, 256>>>();
    k_gemm<<<dim3(6, 16, 2), 256>>>(x_cls, W_cls, x_reg, W_reg);
    k_norm<<<Nn, 256>>>(out);
    for (int h = 0; h < Hh; h++) {
        k_logits<<<dim3(16, 16), 256>>>(h);
        k_wx<<<dim3(8, 32), 256>>>(h, out);
    }
    k_sim<<<Nn, 256>>>(out);
}